// round 1
// baseline (speedup 1.0000x reference)
#include <cuda_runtime.h>

#define NB 512
#define NR 196
#define DV 1024
#define DH 512
#define DA 256
#define RT 32
#define NCHUNK 7          // ceil(196/32)
#define PAD 34            // even pad: 8B-aligned rows for LDS.64, 2-way-conflict scalar access
#define NEG_BIG -3.0e38f

typedef unsigned long long u64;

__device__ float g_hproj[NB * DA];

static __device__ __forceinline__ u64 pack2(float lo, float hi) {
    u64 r;
    asm("mov.b64 %0, {%1, %2};" : "=l"(r) : "f"(lo), "f"(hi));
    return r;
}
static __device__ __forceinline__ u64 fma2(u64 a, u64 b, u64 c) {
    u64 d;
    asm("fma.rn.f32x2 %0, %1, %2, %3;" : "=l"(d) : "l"(a), "l"(b), "l"(c));
    return d;
}
static __device__ __forceinline__ float2 unpack2(u64 v) {
    float lo, hi;
    asm("mov.b64 {%0, %1}, %2;" : "=f"(lo), "=f"(hi) : "l"(v));
    return make_float2(lo, hi);
}

// h_proj[b][a] = hidden[b] . Wh[:,a] + bh[a]   (tiny: 134 MFLOP total)
__global__ __launch_bounds__(DA, 1) void hproj_kernel(
    const float* __restrict__ hidden, const float* __restrict__ Wh,
    const float* __restrict__ bh)
{
    const int b = blockIdx.x, a = threadIdx.x;
    const float* h = hidden + b * DH;
    const float* w = Wh + a;
    float acc = bh[a];
#pragma unroll 8
    for (int k = 0; k < DH; k++)
        acc = fmaf(h[k], w[k * DA], acc);
    g_hproj[b * DA + a] = acc;
}

// One CTA per batch. Online-softmax fused: visual_features read from GMEM exactly once.
// SMEM: vfS[DV][PAD] transposed chunk; red[RT][DA+1] score partials; hp[DA]; sc/es[RT]; misc[4].
__global__ __launch_bounds__(DA, 1) void fused_kernel(
    const float* __restrict__ visual,
    const float* __restrict__ Wv,
    const float* __restrict__ bv,
    const float* __restrict__ Wa,
    float* __restrict__ out)
{
    extern __shared__ float smem[];
    float* vfS  = smem;                     // DV * PAD floats
    float* red  = vfS + DV * PAD;           // RT * (DA+1)
    float* hp   = red + RT * (DA + 1);      // DA
    float* sc   = hp + DA;                  // RT
    float* es   = sc + RT;                  // RT
    float* misc = es + RT;                  // [0]=running max, [1]=denominator, [2]=rescale

    const int b = blockIdx.x;
    const int t = threadIdx.x;              // = attention column a
    const float* vb = visual + (size_t)b * NR * DV;

    hp[t] = g_hproj[b * DA + t] + bv[t];
    const float wa = Wa[t];
    if (t == 0) { misc[0] = NEG_BIG; misc[1] = 0.0f; misc[2] = 0.0f; }
    float num0 = 0.f, num1 = 0.f, num2 = 0.f, num3 = 0.f;   // dims t, t+256, t+512, t+768
    __syncthreads();

    for (int c = 0; c < NCHUNK; c++) {
        const int r0 = c * RT;

        // ---- stage chunk, transposed [d][rr], zero-padded past R ----
        for (int idx = t; idx < RT * DV; idx += DA) {
            int rr = idx >> 10;
            int d  = idx & (DV - 1);
            int r  = r0 + rr;
            vfS[d * PAD + rr] = (r < NR) ? vb[(size_t)r * DV + d] : 0.0f;
        }
        __syncthreads();

        // ---- v_proj GEMM: acc[rowpair] over K, f32x2 packed over row pairs ----
        u64 acc[RT / 2];
#pragma unroll
        for (int p = 0; p < RT / 2; p++) acc[p] = 0ull;

        const float* wcol = Wv + t;         // Wv[k][t], coalesced per warp, L2-resident
        float w0 = wcol[0];
        float w1 = wcol[DA];
        for (int k = 0; k < DV; k += 2) {
            float wn0 = 0.f, wn1 = 0.f;
            if (k + 2 < DV) {               // 2-deep prefetch to cover L2 latency
                wn0 = wcol[(k + 2) * DA];
                wn1 = wcol[(k + 3) * DA];
            }
            u64 wv0 = pack2(w0, w0);
            u64 wv1 = pack2(w1, w1);
            const u64* row0 = (const u64*)(vfS + k * PAD);
            const u64* row1 = (const u64*)(vfS + (k + 1) * PAD);
#pragma unroll
            for (int p = 0; p < RT / 2; p++) {
                acc[p] = fma2(row0[p], wv0, acc[p]);
                acc[p] = fma2(row1[p], wv1, acc[p]);
            }
            w0 = wn0; w1 = wn1;
        }

        // ---- relu(v_proj + h_proj) * Wa -> per-row partials ----
        const float hval = hp[t];
#pragma unroll
        for (int p = 0; p < RT / 2; p++) {
            float2 v = unpack2(acc[p]);
            red[(2 * p)     * (DA + 1) + t] = fmaxf(v.x + hval, 0.0f) * wa;
            red[(2 * p + 1) * (DA + 1) + t] = fmaxf(v.y + hval, 0.0f) * wa;
        }
        __syncthreads();

        // ---- reduce each row over DA=256 columns (warp w owns rows 4w..4w+3) ----
        {
            const int w = t >> 5, lane = t & 31;
#pragma unroll
            for (int q = 0; q < 4; q++) {
                int rr = w * 4 + q;
                const float* row = red + rr * (DA + 1);
                float s = 0.0f;
#pragma unroll
                for (int i = 0; i < DA / 32; i++) s += row[lane + i * 32];
#pragma unroll
                for (int off = 16; off; off >>= 1)
                    s += __shfl_xor_sync(0xffffffffu, s, off);
                if (lane == 0) sc[rr] = (r0 + rr < NR) ? s : NEG_BIG;
            }
        }
        __syncthreads();

        // ---- online softmax state update (ba dropped: softmax shift-invariant) ----
        if (t == 0) {
            float m_old = misc[0];
            float m_new = m_old;
#pragma unroll
            for (int rr = 0; rr < RT; rr++) m_new = fmaxf(m_new, sc[rr]);
            float scl = __expf(m_old - m_new);      // first chunk: underflows to 0
            float den = misc[1] * scl;
#pragma unroll
            for (int rr = 0; rr < RT; rr++) {
                float e = __expf(sc[rr] - m_new);   // masked rows -> 0
                es[rr] = e;
                den += e;
            }
            misc[0] = m_new; misc[1] = den; misc[2] = scl;
        }
        __syncthreads();

        // ---- accumulate numerator from the chunk still in SMEM (no GMEM re-read) ----
        {
            const float scl = misc[2];
            float s0 = 0.f, s1 = 0.f, s2 = 0.f, s3 = 0.f;
#pragma unroll
            for (int rr = 0; rr < RT; rr++) {
                float e = es[rr];
                s0 = fmaf(e, vfS[(t         ) * PAD + rr], s0);
                s1 = fmaf(e, vfS[(t +     DA) * PAD + rr], s1);
                s2 = fmaf(e, vfS[(t + 2 * DA) * PAD + rr], s2);
                s3 = fmaf(e, vfS[(t + 3 * DA) * PAD + rr], s3);
            }
            num0 = num0 * scl + s0;
            num1 = num1 * scl + s1;
            num2 = num2 * scl + s2;
            num3 = num3 * scl + s3;
        }
        __syncthreads();   // before next chunk overwrites vfS/red/es
    }

    const float inv = 1.0f / misc[1];
    out[(size_t)b * DV + t         ] = num0 * inv;
    out[(size_t)b * DV + t +     DA] = num1 * inv;
    out[(size_t)b * DV + t + 2 * DA] = num2 * inv;
    out[(size_t)b * DV + t + 3 * DA] = num3 * inv;
}

extern "C" void kernel_launch(void* const* d_in, const int* in_sizes, int n_in,
                              void* d_out, int out_size) {
    const float* visual = (const float*)d_in[0];
    const float* hidden = (const float*)d_in[1];
    const float* Wv     = (const float*)d_in[2];
    const float* bv     = (const float*)d_in[3];
    const float* Wh     = (const float*)d_in[4];
    const float* bh     = (const float*)d_in[5];
    const float* Wa     = (const float*)d_in[6];
    // d_in[7] = ba: additive constant over regions -> softmax-invariant, intentionally unused
    float* out = (float*)d_out;
    (void)in_sizes; (void)n_in; (void)out_size;

    const int smem_bytes = (DV * PAD + RT * (DA + 1) + DA + RT + RT + 4) * (int)sizeof(float);
    cudaFuncSetAttribute(fused_kernel, cudaFuncAttributeMaxDynamicSharedMemorySize, smem_bytes);

    hproj_kernel<<<NB, DA>>>(hidden, Wh, bh);
    fused_kernel<<<NB, DA, smem_bytes>>>(visual, Wv, bv, Wa, out);
}

// round 3
// speedup vs baseline: 4.6555x; 4.6555x over previous
#include <cuda_runtime.h>
#include <cstdint>

#define NB 512
#define NR 196
#define DV 1024
#define DH 512
#define DA 256
#define KC 32
#define NCHUNKS 128           // 4 M-chunks x 32 K-chunks
#define TPB 256
#define AP 36                 // A smem pitch (floats) -> conflict-free frag loads
#define BP 264                // B smem pitch (floats) -> conflict-free frag loads
#define A_STAGE (64 * AP)     // 2304 floats
#define B_STAGE (KC * BP)     // 8448 floats
#define SMEM_FLOATS (2 * A_STAGE + 2 * B_STAGE + DA + DA + DA + 8)
#define SMEM_BYTES (SMEM_FLOATS * 4)

__device__ float g_Wv[DV * DA];     // Wv pre-rounded to tf32 (rna), layout [k][a]
__device__ float g_hproj[NB * DA];

// ---------------- helpers ----------------
static __device__ __forceinline__ uint32_t smem_u32(const void* p) {
    uint32_t a;
    asm("{ .reg .u64 t; cvta.to.shared.u64 t, %1; cvt.u32.u64 %0, t; }" : "=r"(a) : "l"(p));
    return a;
}
static __device__ __forceinline__ void cpa16(uint32_t dst, const void* src) {
    asm volatile("cp.async.cg.shared.global [%0], [%1], 16;" :: "r"(dst), "l"(src));
}
static __device__ __forceinline__ void cpa_commit() {
    asm volatile("cp.async.commit_group;" ::: "memory");
}
template <int N> static __device__ __forceinline__ void cpa_wait() {
    asm volatile("cp.async.wait_group %0;" :: "n"(N) : "memory");
}
static __device__ __forceinline__ void sts_zero16(uint32_t dst) {
    asm volatile("st.shared.v4.b32 [%0], {%1,%1,%1,%1};" :: "r"(dst), "r"(0) : "memory");
}
static __device__ __forceinline__ uint32_t to_tf32(float x) {
    uint32_t r;
    asm("cvt.rna.tf32.f32 %0, %1;" : "=r"(r) : "f"(x));
    return r;
}
static __device__ __forceinline__ void mma8(float* c, const uint32_t* a, const uint32_t* b) {
    asm volatile(
        "mma.sync.aligned.m16n8k8.row.col.f32.tf32.tf32.f32 "
        "{%0,%1,%2,%3}, {%4,%5,%6,%7}, {%8,%9}, {%0,%1,%2,%3};"
        : "+f"(c[0]), "+f"(c[1]), "+f"(c[2]), "+f"(c[3])
        : "r"(a[0]), "r"(a[1]), "r"(a[2]), "r"(a[3]), "r"(b[0]), "r"(b[1]));
}

// ---------------- prep kernels ----------------
__global__ __launch_bounds__(DA) void prep_wv(const float* __restrict__ Wv) {
    int i = blockIdx.x * DA + threadIdx.x;          // over DV*DA
    uint32_t r = to_tf32(Wv[i]);
    g_Wv[i] = __uint_as_float(r);
}

__global__ __launch_bounds__(DA, 1) void hproj_kernel(
    const float* __restrict__ hidden, const float* __restrict__ Wh,
    const float* __restrict__ bh)
{
    const int b = blockIdx.x, a = threadIdx.x;
    const float* h = hidden + b * DH;
    const float* w = Wh + a;
    float acc = bh[a];
#pragma unroll 8
    for (int k = 0; k < DH; k++) acc = fmaf(h[k], w[k * DA], acc);
    g_hproj[b * DA + a] = acc;
}

// ---------------- staging (double-buffered cp.async) ----------------
static __device__ __forceinline__ void stage_chunk(int idx, uint32_t sA, uint32_t sB,
                                                   const float* __restrict__ vb, int t) {
    const int mc = idx >> 5, kc = idx & 31, buf = idx & 1;
    const int k0 = kc * KC;
    const uint32_t aB = sA + buf * (A_STAGE * 4);
    const uint32_t bB = sB + buf * (B_STAGE * 4);
#pragma unroll
    for (int i = 0; i < 2; i++) {                 // A: 64 rows x 8 segs of 16B
        int s = t + i * TPB;
        int row = s >> 3, seg = s & 7;
        int gr = mc * 64 + row;
        uint32_t dst = aB + row * (AP * 4) + seg * 16;
        if (gr < NR) cpa16(dst, vb + (size_t)gr * DV + k0 + seg * 4);
        else         sts_zero16(dst);
    }
#pragma unroll
    for (int i = 0; i < 8; i++) {                 // B: 32 k-rows x 64 segs of 16B
        int s = t + i * TPB;
        int kr = s >> 6, seg = s & 63;
        uint32_t dst = bB + kr * (BP * 4) + seg * 16;
        cpa16(dst, g_Wv + (size_t)(k0 + kr) * DA + seg * 4);
    }
}

// ---------------- fused kernel: one CTA per batch ----------------
__global__ __launch_bounds__(TPB, 2) void fused_kernel(
    const float* __restrict__ visual,
    const float* __restrict__ bv,
    const float* __restrict__ Wa,
    float* __restrict__ out)
{
    extern __shared__ float smem[];
    float* As  = smem;
    float* Bs  = smem + 2 * A_STAGE;
    float* hpS = Bs + 2 * B_STAGE;
    float* waS = hpS + DA;
    float* scS = waS + DA;
    float* red = scS + DA;

    const int b = blockIdx.x, t = threadIdx.x;
    const int wid = t >> 5, lane = t & 31, g = lane >> 2, tg = lane & 3;
    const int warp_m = wid >> 2, warp_n = wid & 3;    // 2 x 4 warp grid: 64 rows x 256 cols
    const float* vb = visual + (size_t)b * NR * DV;

    hpS[t] = g_hproj[b * DA + t] + bv[t];
    waS[t] = Wa[t];
    scS[t] = 0.0f;

    const uint32_t sA = smem_u32(As), sB = smem_u32(Bs);

    stage_chunk(0, sA, sB, vb, t);
    cpa_commit();

    float acc[2][8][4];
#pragma unroll
    for (int mf = 0; mf < 2; mf++)
#pragma unroll
        for (int nf = 0; nf < 8; nf++)
#pragma unroll
            for (int i = 0; i < 4; i++) acc[mf][nf][i] = 0.0f;

    for (int mc = 0; mc < 4; mc++) {
        for (int kc = 0; kc < 32; kc++) {
            const int idx = mc * 32 + kc;
            if (idx) __syncthreads();                  // protect buffer about to be restaged
            if (idx + 1 < NCHUNKS) {
                stage_chunk(idx + 1, sA, sB, vb, t);
                cpa_commit();
                cpa_wait<1>();                         // chunk idx landed
            } else {
                cpa_wait<0>();
            }
            __syncthreads();

            const int buf = idx & 1;
            const float* A = As + buf * A_STAGE + (warp_m * 32) * AP;
            const float* B = Bs + buf * B_STAGE + warp_n * 64;
#pragma unroll
            for (int ks = 0; ks < 4; ks++) {
                const int kk = ks * 8;
                uint32_t a[2][4];
#pragma unroll
                for (int mf = 0; mf < 2; mf++) {
                    const float* ar  = A + (mf * 16 + g) * AP;
                    const float* ar8 = ar + 8 * AP;
                    a[mf][0] = to_tf32(ar [kk + tg]);
                    a[mf][1] = to_tf32(ar8[kk + tg]);
                    a[mf][2] = to_tf32(ar [kk + tg + 4]);
                    a[mf][3] = to_tf32(ar8[kk + tg + 4]);
                }
                uint32_t bb[8][2];
#pragma unroll
                for (int nf = 0; nf < 8; nf++) {
                    const float* br = B + (kk + tg) * BP + nf * 8 + g;
                    bb[nf][0] = __float_as_uint(br[0]);
                    bb[nf][1] = __float_as_uint(br[4 * BP]);
                }
#pragma unroll
                for (int mf = 0; mf < 2; mf++)
#pragma unroll
                    for (int nf = 0; nf < 8; nf++)
                        mma8(acc[mf][nf], a[mf], bb[nf]);
            }
        }

        // ---- per-M-chunk score epilogue: relu(c+hp)*wa, reduce over 256 cols ----
        {
            float pA[2] = {0.0f, 0.0f}, pB[2] = {0.0f, 0.0f};
#pragma unroll
            for (int nf = 0; nf < 8; nf++) {
                const int col = warp_n * 64 + nf * 8 + 2 * tg;
                const float hp0 = hpS[col], hp1 = hpS[col + 1];
                const float wa0 = waS[col], wa1 = waS[col + 1];
#pragma unroll
                for (int mf = 0; mf < 2; mf++) {
                    pA[mf] += fmaxf(acc[mf][nf][0] + hp0, 0.0f) * wa0
                            + fmaxf(acc[mf][nf][1] + hp1, 0.0f) * wa1;
                    pB[mf] += fmaxf(acc[mf][nf][2] + hp0, 0.0f) * wa0
                            + fmaxf(acc[mf][nf][3] + hp1, 0.0f) * wa1;
                    acc[mf][nf][0] = acc[mf][nf][1] = 0.0f;
                    acc[mf][nf][2] = acc[mf][nf][3] = 0.0f;
                }
            }
#pragma unroll
            for (int mf = 0; mf < 2; mf++) {
                pA[mf] += __shfl_xor_sync(0xffffffffu, pA[mf], 1);
                pA[mf] += __shfl_xor_sync(0xffffffffu, pA[mf], 2);
                pB[mf] += __shfl_xor_sync(0xffffffffu, pB[mf], 1);
                pB[mf] += __shfl_xor_sync(0xffffffffu, pB[mf], 2);
                if (tg == 0) {
                    const int r0 = mc * 64 + warp_m * 32 + mf * 16 + g;
                    atomicAdd(&scS[r0],     pA[mf]);
                    atomicAdd(&scS[r0 + 8], pB[mf]);
                }
            }
        }
    }
    __syncthreads();

    // ---- softmax over 196 scores ----
    const float sval = (t < NR) ? scS[t] : -3.0e38f;
    float v = sval;
#pragma unroll
    for (int off = 16; off; off >>= 1) v = fmaxf(v, __shfl_xor_sync(0xffffffffu, v, off));
    if (lane == 0) red[wid] = v;
    __syncthreads();
    float m = red[0];
#pragma unroll
    for (int w = 1; w < 8; w++) m = fmaxf(m, red[w]);

    const float e = (t < NR) ? __expf(sval - m) : 0.0f;
    float se = e;
#pragma unroll
    for (int off = 16; off; off >>= 1) se += __shfl_xor_sync(0xffffffffu, se, off);
    __syncthreads();
    if (lane == 0) red[wid] = se;
    __syncthreads();
    float den = 0.0f;
#pragma unroll
    for (int w = 0; w < 8; w++) den += red[w];
    scS[t] = e * (1.0f / den);          // attention weights
    __syncthreads();

    // ---- att_output[b][:] = sum_r att[r] * visual[b][r][:] (coalesced float4) ----
    {
        const float4* vb4 = (const float4*)vb;
        float4 o = make_float4(0.f, 0.f, 0.f, 0.f);
#pragma unroll 4
        for (int r = 0; r < NR; r++) {
            const float w = scS[r];
            const float4 x = vb4[r * (DV / 4) + t];
            o.x = fmaf(w, x.x, o.x);
            o.y = fmaf(w, x.y, o.y);
            o.z = fmaf(w, x.z, o.z);
            o.w = fmaf(w, x.w, o.w);
        }
        ((float4*)out)[(size_t)b * (DV / 4) + t] = o;
    }
}

extern "C" void kernel_launch(void* const* d_in, const int* in_sizes, int n_in,
                              void* d_out, int out_size) {
    const float* visual = (const float*)d_in[0];
    const float* hidden = (const float*)d_in[1];
    const float* Wv     = (const float*)d_in[2];
    const float* bv     = (const float*)d_in[3];
    const float* Wh     = (const float*)d_in[4];
    const float* bh     = (const float*)d_in[5];
    const float* Wa     = (const float*)d_in[6];
    // d_in[7] = ba: additive constant over regions -> softmax-invariant, intentionally unused
    float* out = (float*)d_out;
    (void)in_sizes; (void)n_in; (void)out_size;

    cudaFuncSetAttribute(fused_kernel, cudaFuncAttributeMaxDynamicSharedMemorySize, SMEM_BYTES);

    prep_wv<<<DV, DA>>>(Wv);
    hproj_kernel<<<NB, DA>>>(hidden, Wh, bh);
    fused_kernel<<<NB, TPB, SMEM_BYTES>>>(visual, bv, Wa, out);
}

// round 4
// speedup vs baseline: 5.1462x; 1.1054x over previous
#include <cuda_runtime.h>
#include <cstdint>

#define NB 512
#define NR 196
#define DV 1024
#define DH 512
#define DA 256
#define KC 32
#define TPB 256
#define AP 36                   // A smem pitch (floats) -> conflict-free frag loads
#define A_STAGE (64 * AP)       // 2304 floats
#define B_STAGE (KC * DA)       // 8192 floats (fragment-major, no pitch needed)
#define SMEM_FLOATS (2 * A_STAGE + 2 * B_STAGE + DA + DA + DA + 8)
#define SMEM_BYTES (SMEM_FLOATS * 4)

__device__ float g_Wv[DV * DA];     // tf32-rounded Wv, fragment-major [kc][ks][wn][m][lane][4]
__device__ float g_hproj[NB * DA];

// ---------------- helpers ----------------
static __device__ __forceinline__ uint32_t smem_u32(const void* p) {
    uint32_t a;
    asm("{ .reg .u64 t; cvta.to.shared.u64 t, %1; cvt.u32.u64 %0, t; }" : "=r"(a) : "l"(p));
    return a;
}
static __device__ __forceinline__ void cpa16(uint32_t dst, const void* src) {
    asm volatile("cp.async.cg.shared.global [%0], [%1], 16;" :: "r"(dst), "l"(src));
}
static __device__ __forceinline__ void cpa_commit() {
    asm volatile("cp.async.commit_group;" ::: "memory");
}
template <int N> static __device__ __forceinline__ void cpa_wait() {
    asm volatile("cp.async.wait_group %0;" :: "n"(N) : "memory");
}
static __device__ __forceinline__ void sts_zero16(uint32_t dst) {
    asm volatile("st.shared.v4.b32 [%0], {%1,%1,%1,%1};" :: "r"(dst), "r"(0) : "memory");
}
static __device__ __forceinline__ uint32_t to_tf32(float x) {
    uint32_t r;
    asm("cvt.rna.tf32.f32 %0, %1;" : "=r"(r) : "f"(x));
    return r;
}
static __device__ __forceinline__ void mma8(float* c, const uint32_t* a, uint32_t b0, uint32_t b1) {
    asm volatile(
        "mma.sync.aligned.m16n8k8.row.col.f32.tf32.tf32.f32 "
        "{%0,%1,%2,%3}, {%4,%5,%6,%7}, {%8,%9}, {%0,%1,%2,%3};"
        : "+f"(c[0]), "+f"(c[1]), "+f"(c[2]), "+f"(c[3])
        : "r"(a[0]), "r"(a[1]), "r"(a[2]), "r"(a[3]), "r"(b0), "r"(b1));
}

// ---------------- prep: Wv -> tf32-rounded, fragment-major ----------------
// dst idx = ((((kc*4 + ks)*4 + wn)*4 + m)*32 + lane)*4 + j
// col = wn*64 + 16*m + 8*(j>>1) + (lane>>2);  k = kc*32 + ks*8 + (lane&3) + 4*(j&1)
__global__ __launch_bounds__(DA) void prep_wv(const float* __restrict__ Wv) {
    const int idx = blockIdx.x * DA + threadIdx.x;
    const int j    = idx & 3;
    const int lane = (idx >> 2) & 31;
    const int m    = (idx >> 7) & 3;
    const int wn   = (idx >> 9) & 3;
    const int ks   = (idx >> 11) & 3;
    const int kc   = idx >> 13;
    const int col = wn * 64 + 16 * m + 8 * (j >> 1) + (lane >> 2);
    const int k   = kc * 32 + ks * 8 + (lane & 3) + 4 * (j & 1);
    g_Wv[idx] = __uint_as_float(to_tf32(Wv[k * DA + col]));
}

__global__ __launch_bounds__(DA, 1) void hproj_kernel(
    const float* __restrict__ hidden, const float* __restrict__ Wh,
    const float* __restrict__ bh)
{
    const int b = blockIdx.x, a = threadIdx.x;
    const float* h = hidden + b * DH;
    const float* w = Wh + a;
    float acc = bh[a];
#pragma unroll 8
    for (int k = 0; k < DH; k++) acc = fmaf(h[k], w[k * DA], acc);
    g_hproj[b * DA + a] = acc;
}

// ---------------- staging (double-buffered cp.async) ----------------
static __device__ __forceinline__ void stage_chunk(int idx, uint32_t sA, uint32_t sB,
                                                   const float* __restrict__ vb, int t) {
    const int mc = idx >> 5, kc = idx & 31, buf = idx & 1;
    const int k0 = kc * KC;
    const uint32_t aB = sA + buf * (A_STAGE * 4);
    const uint32_t bB = sB + buf * (B_STAGE * 4);
#pragma unroll
    for (int i = 0; i < 2; i++) {                 // A: 64 rows x 8 segs of 16B
        int s = t + i * TPB;
        int row = s >> 3, seg = s & 7;
        int gr = mc * 64 + row;
        uint32_t dst = aB + row * (AP * 4) + seg * 16;
        if (gr < NR) cpa16(dst, vb + (size_t)gr * DV + k0 + seg * 4);
        else         sts_zero16(dst);
    }
    const float* bsrc = g_Wv + (size_t)kc * B_STAGE;
#pragma unroll
    for (int i = 0; i < 8; i++) {                 // B: flat 32KB fragment-major copy
        int s = t + i * TPB;
        cpa16(bB + s * 16, bsrc + s * 4);
    }
}

// ---------------- fused kernel: one CTA per batch ----------------
__global__ __launch_bounds__(TPB, 2) void fused_kernel(
    const float* __restrict__ visual,
    const float* __restrict__ bv,
    const float* __restrict__ Wa,
    float* __restrict__ out)
{
    extern __shared__ float smem[];
    float* As  = smem;
    float* Bs  = smem + 2 * A_STAGE;
    float* hpS = Bs + 2 * B_STAGE;
    float* waS = hpS + DA;
    float* scS = waS + DA;
    float* red = scS + DA;

    const int b = blockIdx.x, t = threadIdx.x;
    const int wid = t >> 5, lane = t & 31, g = lane >> 2, tg = lane & 3;
    const int warp_m = wid >> 2, warp_n = wid & 3;    // 2 x 4 warp grid: 64 rows x 256 cols
    const float* vb = visual + (size_t)b * NR * DV;

    hpS[t] = g_hproj[b * DA + t] + bv[t];
    waS[t] = Wa[t];
    scS[t] = 0.0f;

    const uint32_t sA = smem_u32(As), sB = smem_u32(Bs);

    stage_chunk(0, sA, sB, vb, t);
    cpa_commit();

    float acc[2][8][4];
#pragma unroll
    for (int mf = 0; mf < 2; mf++)
#pragma unroll
        for (int nf = 0; nf < 8; nf++)
#pragma unroll
            for (int i = 0; i < 4; i++) acc[mf][nf][i] = 0.0f;

    for (int mc = 0; mc < 4; mc++) {
        // tail chunk (rows 192..255): only rows 192..207 are interesting
        const int nmf = (mc == 3) ? ((warp_m == 0) ? 1 : 0) : 2;

        for (int kc = 0; kc < 32; kc++) {
            const int idx = mc * 32 + kc;
            if (idx) __syncthreads();                  // all warps done with buffer being restaged
            if (idx + 1 < 128) {
                stage_chunk(idx + 1, sA, sB, vb, t);
                cpa_commit();
                cpa_wait<1>();                         // chunk idx landed
            } else {
                cpa_wait<0>();
            }
            __syncthreads();

            const int buf = idx & 1;
            const float*  A  = As + buf * A_STAGE + (warp_m * 32) * AP;
            const float4* Bf = (const float4*)(Bs + buf * B_STAGE) + (warp_n * 4) * 32 + lane;
#pragma unroll
            for (int ks = 0; ks < 4; ks++) {
                const int kk = ks * 8;
                uint32_t a[2][4];
#pragma unroll
                for (int mf = 0; mf < 2; mf++) {
                    if (mf < nmf) {
                        const float* ar  = A + (mf * 16 + g) * AP + kk + tg;
                        a[mf][0] = __float_as_uint(ar[0]);
                        a[mf][1] = __float_as_uint(ar[8 * AP]);
                        a[mf][2] = __float_as_uint(ar[4]);
                        a[mf][3] = __float_as_uint(ar[8 * AP + 4]);
                    }
                }
                const float4* Bk = Bf + (ks * 16) * 32;    // [ks][wn] block, this lane
#pragma unroll
                for (int m = 0; m < 4; m++) {
                    const float4 f = Bk[m * 32];
                    const uint32_t b00 = __float_as_uint(f.x), b01 = __float_as_uint(f.y);
                    const uint32_t b10 = __float_as_uint(f.z), b11 = __float_as_uint(f.w);
#pragma unroll
                    for (int mf = 0; mf < 2; mf++) {
                        if (mf < nmf) {
                            mma8(acc[mf][2 * m],     a[mf], b00, b01);
                            mma8(acc[mf][2 * m + 1], a[mf], b10, b11);
                        }
                    }
                }
            }
        }

        // ---- per-M-chunk score epilogue: relu(c+hp)*wa, reduce over 256 cols ----
        {
            float pA[2] = {0.0f, 0.0f}, pB[2] = {0.0f, 0.0f};
#pragma unroll
            for (int nf = 0; nf < 8; nf++) {
                const int col = warp_n * 64 + nf * 8 + 2 * tg;
                const float hp0 = hpS[col], hp1 = hpS[col + 1];
                const float wa0 = waS[col], wa1 = waS[col + 1];
#pragma unroll
                for (int mf = 0; mf < 2; mf++) {
                    if (mf < nmf) {
                        pA[mf] += fmaxf(acc[mf][nf][0] + hp0, 0.0f) * wa0
                                + fmaxf(acc[mf][nf][1] + hp1, 0.0f) * wa1;
                        pB[mf] += fmaxf(acc[mf][nf][2] + hp0, 0.0f) * wa0
                                + fmaxf(acc[mf][nf][3] + hp1, 0.0f) * wa1;
                        acc[mf][nf][0] = acc[mf][nf][1] = 0.0f;
                        acc[mf][nf][2] = acc[mf][nf][3] = 0.0f;
                    }
                }
            }
#pragma unroll
            for (int mf = 0; mf < 2; mf++) {
                if (mf < nmf) {
                    pA[mf] += __shfl_xor_sync(0xffffffffu, pA[mf], 1);
                    pA[mf] += __shfl_xor_sync(0xffffffffu, pA[mf], 2);
                    pB[mf] += __shfl_xor_sync(0xffffffffu, pB[mf], 1);
                    pB[mf] += __shfl_xor_sync(0xffffffffu, pB[mf], 2);
                    if (tg == 0) {
                        const int r0 = mc * 64 + warp_m * 32 + mf * 16 + g;
                        atomicAdd(&scS[r0],     pA[mf]);
                        atomicAdd(&scS[r0 + 8], pB[mf]);
                    }
                }
            }
        }
    }
    __syncthreads();

    // ---- softmax over 196 scores ----
    const float sval = (t < NR) ? scS[t] : -3.0e38f;
    float v = sval;
#pragma unroll
    for (int off = 16; off; off >>= 1) v = fmaxf(v, __shfl_xor_sync(0xffffffffu, v, off));
    if (lane == 0) red[wid] = v;
    __syncthreads();
    float m = red[0];
#pragma unroll
    for (int w = 1; w < 8; w++) m = fmaxf(m, red[w]);

    const float e = (t < NR) ? __expf(sval - m) : 0.0f;
    float se = e;
#pragma unroll
    for (int off = 16; off; off >>= 1) se += __shfl_xor_sync(0xffffffffu, se, off);
    __syncthreads();
    if (lane == 0) red[wid] = se;
    __syncthreads();
    float den = 0.0f;
#pragma unroll
    for (int w = 0; w < 8; w++) den += red[w];
    scS[t] = e * (1.0f / den);          // attention weights
    __syncthreads();

    // ---- att_output[b][:] = sum_r att[r] * visual[b][r][:] (coalesced float4) ----
    {
        const float4* vb4 = (const float4*)vb;
        float4 o = make_float4(0.f, 0.f, 0.f, 0.f);
#pragma unroll 4
        for (int r = 0; r < NR; r++) {
            const float w = scS[r];
            const float4 x = vb4[r * (DV / 4) + t];
            o.x = fmaf(w, x.x, o.x);
            o.y = fmaf(w, x.y, o.y);
            o.z = fmaf(w, x.z, o.z);
            o.w = fmaf(w, x.w, o.w);
        }
        ((float4*)out)[(size_t)b * (DV / 4) + t] = o;
    }
}

extern "C" void kernel_launch(void* const* d_in, const int* in_sizes, int n_in,
                              void* d_out, int out_size) {
    const float* visual = (const float*)d_in[0];
    const float* hidden = (const float*)d_in[1];
    const float* Wv     = (const float*)d_in[2];
    const float* bv     = (const float*)d_in[3];
    const float* Wh     = (const float*)d_in[4];
    const float* bh     = (const float*)d_in[5];
    const float* Wa     = (const float*)d_in[6];
    // d_in[7] = ba: additive constant over regions -> softmax-invariant, intentionally unused
    float* out = (float*)d_out;
    (void)in_sizes; (void)n_in; (void)out_size;

    cudaFuncSetAttribute(fused_kernel, cudaFuncAttributeMaxDynamicSharedMemorySize, SMEM_BYTES);

    prep_wv<<<DV, DA>>>(Wv);
    hproj_kernel<<<NB, DA>>>(hidden, Wh, bh);
    fused_kernel<<<NB, TPB, SMEM_BYTES>>>(visual, bv, Wa, out);
}